// round 8
// baseline (speedup 1.0000x reference)
#include <cuda_runtime.h>
#include <math.h>
#include <cstdint>

#define NB 64
#define NS 512
#define NF 1024
#define SST 36   // gemm smem row stride in floats

static __device__ float g_P[NB * NS * NF];      // x_proj, [b][s][h]
static __device__ float g_H[NB * NS * NF];      // x_rounded, then hidden states (tf32-rounded)
static __device__ float g_Wx[NF * NF];          // tf32-rounded W_x
static __device__ float g_Who[NF * NF];         // tf32-rounded W_ho
static __device__ float g_ring[2 * 1032 * 64];  // transposed h ring [slot][k][b]
static __device__ unsigned g_ctr[2 * NS];       // per-(step,group) arrival counters

typedef unsigned long long ull;

__device__ __forceinline__ ull pack2(float x) {
    ull r; asm("mov.b64 %0, {%1, %1};" : "=l"(r) : "f"(x)); return r;
}
__device__ __forceinline__ float2 unpack2(ull v) {
    float2 r; asm("mov.b64 {%0, %1}, %2;" : "=f"(r.x), "=f"(r.y) : "l"(v)); return r;
}
__device__ __forceinline__ void fma2(ull& d, ull a, ull b) {
    asm("fma.rn.f32x2 %0, %1, %2, %0;" : "+l"(d) : "l"(a), "l"(b));
}
__device__ __forceinline__ void add2(ull& d, ull a) {
    asm("add.rn.f32x2 %0, %0, %1;" : "+l"(d) : "l"(a));
}
__device__ __forceinline__ float tf32r(float x) {
    float r; asm("cvt.rna.tf32.f32 %0, %1;" : "=f"(r) : "f"(x)); return r;
}
__device__ __forceinline__ uint32_t smem_u32(const void* p) {
    uint32_t a;
    asm("{ .reg .u64 t; cvta.to.shared.u64 t, %1; cvt.u32.u64 %0, t; }" : "=r"(a) : "l"(p));
    return a;
}
__device__ __forceinline__ void cp_async16(uint32_t dst, const void* src) {
    asm volatile("cp.async.cg.shared.global [%0], [%1], 16;" :: "r"(dst), "l"(src) : "memory");
}
__device__ __forceinline__ void mma_m16n8k8(float* c, const uint32_t* a,
                                            uint32_t b0, uint32_t b1) {
    asm volatile(
        "mma.sync.aligned.m16n8k8.row.col.f32.tf32.tf32.f32 "
        "{%0,%1,%2,%3}, {%4,%5,%6,%7}, {%8,%9}, {%0,%1,%2,%3};"
        : "+f"(c[0]), "+f"(c[1]), "+f"(c[2]), "+f"(c[3])
        : "r"(a[0]), "r"(a[1]), "r"(a[2]), "r"(a[3]), "r"(b0), "r"(b1));
}

__global__ void knop() {}

// ---------------------------------------------------------------------------
// Fused init: tf32-round x -> g_H, round weights, ring slot 1 <- h0^T, ctrs.
// ---------------------------------------------------------------------------
__global__ void fused_init(const float* __restrict__ x,
                           const float* __restrict__ Wih,
                           const float* __restrict__ Who,
                           const float* __restrict__ h0)
{
    int i = blockIdx.x * 256 + threadIdx.x;   // float4 idx
    float4 v = ((const float4*)x)[i];
    v.x = tf32r(v.x); v.y = tf32r(v.y); v.z = tf32r(v.z); v.w = tf32r(v.w);
    ((float4*)g_H)[i] = v;

    if (i < NF * NF) {
        int n = i >> 10, k = i & 1023;
        g_Wx[i]  = tf32r(Wih[(size_t)n * 2048 + k]);
        g_Who[i] = tf32r(Who[i]);
    }
    if (i < 65536) {
        int k = i >> 6, b = i & 63;
        g_ring[1032 * 64 + k * 64 + b] = h0[b * 1024 + k];
    }
    if (i < 2 * NS) g_ctr[i] = 0u;
}

// ---------------------------------------------------------------------------
// tf32 mma.sync GEMM (unchanged; 603 us measured).
// ---------------------------------------------------------------------------
__global__ void __launch_bounds__(256, 2) gemm_mma(
    const float* __restrict__ A, const float* __restrict__ B,
    const float* __restrict__ bias, float* __restrict__ C)
{
    extern __shared__ float sm[];
    const int tid = threadIdx.x;
    const int wid = tid >> 5, lane = tid & 31;
    const int g = lane >> 2, tig = lane & 3;
    const int bm = blockIdx.y * 128, bn = blockIdx.x * 128;
    const int mbase = (wid >> 1) * 32, nbase = (wid & 1) * 64;

    const int BUF = 128 * SST;
    const uint32_t sbase = smem_u32(sm);

    const int lrow = tid >> 1, lk = (tid & 1) * 16;
    const float* Ag = A + (size_t)(bm + lrow) * 1024 + lk;
    const float* Bg = B + (size_t)(bn + lrow) * 1024 + lk;
    const uint32_t dstA = sbase + (uint32_t)(lrow * SST + lk) * 4;
    const uint32_t dstB = dstA + (uint32_t)BUF * 4;

    float acc[2][8][4];
#pragma unroll
    for (int mt = 0; mt < 2; mt++)
#pragma unroll
        for (int nt = 0; nt < 8; nt++)
#pragma unroll
            for (int q = 0; q < 4; q++) acc[mt][nt][q] = 0.f;

    {
#pragma unroll
        for (int j = 0; j < 4; j++) {
            cp_async16(dstA + j * 16, Ag + 4 * j);
            cp_async16(dstB + j * 16, Bg + 4 * j);
        }
        asm volatile("cp.async.commit_group;" ::: "memory");
    }

    for (int c = 0; c < 32; ++c) {
        if (c + 1 < 32) {
            const int st = (c + 1) & 1;
            const float* ag = Ag + (c + 1) * 32;
            const float* bg = Bg + (c + 1) * 32;
            const uint32_t off = (uint32_t)(st * 2 * BUF) * 4;
#pragma unroll
            for (int j = 0; j < 4; j++) {
                cp_async16(dstA + off + j * 16, ag + 4 * j);
                cp_async16(dstB + off + j * 16, bg + 4 * j);
            }
            asm volatile("cp.async.commit_group;" ::: "memory");
            asm volatile("cp.async.wait_group 1;" ::: "memory");
        } else {
            asm volatile("cp.async.wait_group 0;" ::: "memory");
        }
        __syncthreads();

        const float* As_ = sm + (c & 1) * 2 * BUF;
        const float* Bs_ = As_ + BUF;
#pragma unroll
        for (int ks = 0; ks < 4; ks++) {
            const int k = ks * 8;
            uint32_t a[2][4];
#pragma unroll
            for (int mt = 0; mt < 2; mt++) {
                const float* ap = As_ + (mbase + mt * 16 + g) * SST + k + tig;
                a[mt][0] = __float_as_uint(ap[0]);
                a[mt][1] = __float_as_uint(ap[8 * SST]);
                a[mt][2] = __float_as_uint(ap[4]);
                a[mt][3] = __float_as_uint(ap[8 * SST + 4]);
            }
#pragma unroll
            for (int nt = 0; nt < 8; nt++) {
                const float* bp = Bs_ + (nbase + nt * 8 + g) * SST + k + tig;
                uint32_t b0 = __float_as_uint(bp[0]);
                uint32_t b1 = __float_as_uint(bp[4]);
                mma_m16n8k8(acc[0][nt], a[0], b0, b1);
                mma_m16n8k8(acc[1][nt], a[1], b0, b1);
            }
        }
        __syncthreads();
    }

#pragma unroll
    for (int mt = 0; mt < 2; mt++) {
        const size_t r0 = (size_t)(bm + mbase + mt * 16 + g) * 1024;
#pragma unroll
        for (int nt = 0; nt < 8; nt++) {
            const int col = bn + nbase + nt * 8 + 2 * tig;
            float2 bb = *(const float2*)&bias[col];
            float2 v0 = make_float2(acc[mt][nt][0] + bb.x, acc[mt][nt][1] + bb.y);
            float2 v1 = make_float2(acc[mt][nt][2] + bb.x, acc[mt][nt][3] + bb.y);
            *(float2*)&C[r0 + col] = v0;
            *(float2*)&C[r0 + 8 * 1024 + col] = v1;
        }
    }
}

// ---------------------------------------------------------------------------
// Persistent recurrence scan: 128 CTAs x 512 threads, 2 batch-groups of 64.
// Group g owns batches [32g, 32g+32); CTA owns 16 n. W_h slice stored (w,w)-
// DUPLICATED in SMEM (128 KB, 1 CTA/SM). Warp w reduces k in [64w, 64w+64).
// Thread tile: 2 batch-pairs (ONE ulonglong2 LDG.128 from the [k][b] ring =
// natural f32x2 operands, zero packing) x 4 n (2 LDS.128 of dup'd w).
// Inner loop = 11 instr/kk: 1 LDG + 2 LDS + 8 FFMA2.
// Cross-warp reduce: packed f32x2 adds; ring write is one contiguous float2.
// ---------------------------------------------------------------------------
__global__ void __launch_bounds__(512, 1) rnn_scan(const float* __restrict__ Wih)
{
    extern __shared__ ull smu[];
    ull* wsm = smu;            // [1024 k][16 n] dup'd (131072 B)
    ull* red = smu + 16384;    // [16 w][8 q][32 lane] (32768 B)

    const int tid  = threadIdx.x;
    const int warp = tid >> 5, lane = tid & 31;
    const int bq = lane & 7;             // 2 batch-pairs: batches [4*bq, 4*bq+4)
    const int nq = lane >> 3;            // 4 n: [4*nq, 4*nq+4) within CTA slice
    const int kbase = warp * 64;
    const int grp = blockIdx.x & 1;      // batch group
    const int NB0 = (blockIdx.x >> 1) * 16;
    const int B0  = grp * 32;

    // One-time: W_h slice, k-coalesced LDG, duplicated STS to [k][16n].
    for (int idx = tid; idx < 16384; idx += 512) {
        int n = idx >> 10, k = idx & 1023;
        wsm[k * 16 + n] = pack2(Wih[(size_t)(NB0 + n) * 2048 + 1024 + k]);
    }

    // Writer decode (threads 0..255 own one batch-pair x one n).
    const int rq = tid >> 5, rl = tid & 31;            // valid for tid < 256
    const int rb = B0 + 4 * (rl & 7) + 2 * (rq >> 2);  // even batch
    const int rn = NB0 + 4 * (rl >> 3) + (rq & 3);     // n
    const size_t pb0 = ((size_t)rb * NS) * NF + rn;
    const size_t pb1 = pb0 + (size_t)NS * NF;          // batch rb+1

    __syncthreads();

    float pr0 = 0.f, pr1 = 0.f;
    if (tid < 256) {
        pr0 = __ldg(&g_P[pb0]);
        pr1 = __ldg(&g_P[pb1]);
    }

    for (int s = 0; s < NS; ++s) {
        const float* __restrict__ hq =
            g_ring + ((s + 1) & 1) * (1032 * 64) + B0 + 4 * bq;

        ull acc[2][4];
#pragma unroll
        for (int i = 0; i < 2; i++)
#pragma unroll
            for (int j = 0; j < 4; j++) acc[i][j] = 0ull;

        // depth-8 pipelined k loop (padded ring rows: over-read harmless)
        ulonglong2 p[8];
#pragma unroll
        for (int j = 0; j < 8; ++j)
            p[j] = *(const ulonglong2*)(hq + (kbase + j) * 64);
#pragma unroll 8
        for (int kk = 0; kk < 64; ++kk) {
            const int slot = kk & 7;
            ulonglong2 h = p[slot];            // (b0,b1), (b2,b3) natural pairs
            p[slot] = *(const ulonglong2*)(hq + (kbase + kk + 8) * 64);
            const ull* wp = wsm + (kbase + kk) * 16 + 4 * nq;
            ulonglong2 wa = *(const ulonglong2*)wp;        // dup w[n0], w[n1]
            ulonglong2 wb = *(const ulonglong2*)(wp + 2);  // dup w[n2], w[n3]
            fma2(acc[0][0], h.x, wa.x); fma2(acc[0][1], h.x, wa.y);
            fma2(acc[0][2], h.x, wb.x); fma2(acc[0][3], h.x, wb.y);
            fma2(acc[1][0], h.y, wa.x); fma2(acc[1][1], h.y, wa.y);
            fma2(acc[1][2], h.y, wb.x); fma2(acc[1][3], h.y, wb.y);
        }

        // Stash partials (lane-contiguous, conflict-free STS.64).
#pragma unroll
        for (int i = 0; i < 2; i++)
#pragma unroll
            for (int j = 0; j < 4; j++)
                red[((warp * 8) + (i * 4 + j)) * 32 + lane] = acc[i][j];
        __syncthreads();

        float r0 = 0.f, r1 = 0.f;
        if (tid < 256) {
            ull ar = red[(0 * 8 + rq) * 32 + rl];
#pragma unroll
            for (int w2 = 1; w2 < 16; ++w2)
                add2(ar, red[(w2 * 8 + rq) * 32 + rl]);   // packed f32x2 adds
            float2 v = unpack2(ar);
            r0 = tanhf(v.x + pr0);
            r1 = tanhf(v.y + pr1);
            // Ring write: one contiguous float2 (batch-pair in a [k][b] row).
            float* rc = g_ring + (s & 1) * (1032 * 64);
            *(float2*)(rc + rn * 64 + rb) = make_float2(r0, r1);
        }

        if (s != NS - 1) {
            __syncthreads();                    // group ring rows complete
            if (tid == 0) {
                asm volatile("red.release.gpu.global.add.u32 [%0], %1;"
                             :: "l"(&g_ctr[s * 2 + grp]), "r"(1u) : "memory");
            }
            // Overlapped with barrier: g_H writes + next g_P prefetch.
            if (tid < 256) {
                g_H[pb0 + (size_t)s * NF] = tf32r(r0);
                g_H[pb1 + (size_t)s * NF] = tf32r(r1);
                pr0 = __ldg(&g_P[pb0 + (size_t)(s + 1) * NF]);
                pr1 = __ldg(&g_P[pb1 + (size_t)(s + 1) * NF]);
            }
            if (tid == 0) {
                unsigned v;
                do {
                    asm volatile("ld.acquire.gpu.global.u32 %0, [%1];"
                                 : "=r"(v) : "l"(&g_ctr[s * 2 + grp]));
                } while (v < 64u);
            }
            __syncthreads();
        } else {
            if (tid < 256) {
                g_H[pb0 + (size_t)s * NF] = tf32r(r0);
                g_H[pb1 + (size_t)s * NF] = tf32r(r1);
            }
        }
    }
}

extern "C" void kernel_launch(void* const* d_in, const int* in_sizes, int n_in,
                              void* d_out, int out_size)
{
    const float* x   = (const float*)d_in[0];
    const float* h0  = (const float*)d_in[1];
    const float* Wih = (const float*)d_in[2];
    const float* bih = (const float*)d_in[3];
    const float* Who = (const float*)d_in[4];
    const float* bho = (const float*)d_in[5];
    float* out = (float*)d_out;

    float *pP = nullptr, *pH = nullptr, *pWx = nullptr, *pWo = nullptr;
    cudaGetSymbolAddress((void**)&pP, g_P);
    cudaGetSymbolAddress((void**)&pH, g_H);
    cudaGetSymbolAddress((void**)&pWx, g_Wx);
    cudaGetSymbolAddress((void**)&pWo, g_Who);

    const int GEMM_SMEM = 4 * 128 * SST * 4;     // 73728 B
    const int SCAN_SMEM = 131072 + 32768;        // 163840 B

    static bool attr_done = false;
    if (!attr_done) {
        cudaFuncSetAttribute(rnn_scan, cudaFuncAttributeMaxDynamicSharedMemorySize, SCAN_SMEM);
        cudaFuncSetAttribute(gemm_mma, cudaFuncAttributeMaxDynamicSharedMemorySize, GEMM_SMEM);
        attr_done = true;
    }

    // user idx 0: fused init
    fused_init<<<32768, 256>>>(x, Wih, Who, h0);
    // user idx 1: x_proj = x_r @ W_x^T + b_ih -> g_P
    gemm_mma<<<dim3(8, 256), 256, GEMM_SMEM>>>(pH, pWx, bih, pP);
    // user idx 2: pad so profiler (user idx 3) hits the scan
    knop<<<1, 32>>>();
    // user idx 3: persistent recurrence scan  <-- ncu capture
    rnn_scan<<<128, 512, SCAN_SMEM>>>(Wih);
    // user idx 4: out = h_r @ W_ho^T + b_ho
    gemm_mma<<<dim3(8, 256), 256, GEMM_SMEM>>>(pH, pWo, bho, out);
}

// round 9
// speedup vs baseline: 1.1190x; 1.1190x over previous
#include <cuda_runtime.h>
#include <math.h>
#include <cstdint>

#define NB 64
#define NS 512
#define NF 1024
#define SST 36   // gemm smem row stride in floats (conflict-free fragments)

static __device__ float g_P[NB * NS * NF];      // x_proj, [b][s][h]
static __device__ float g_H[NB * NS * NF];      // x_rounded, then hidden states (tf32-rounded)
static __device__ float g_Wx[NF * NF];          // tf32-rounded W_x
static __device__ float g_Who[NF * NF];         // tf32-rounded W_ho
static __device__ float g_ring[2 * 1032 * 64];  // transposed h ring [slot][k][b]
static __device__ unsigned g_ctr[2 * NS];       // per-(step,group) arrival counters

typedef unsigned long long ull;

__device__ __forceinline__ ull pack2(float x) {
    ull r; asm("mov.b64 %0, {%1, %1};" : "=l"(r) : "f"(x)); return r;
}
__device__ __forceinline__ float2 unpack2(ull v) {
    float2 r; asm("mov.b64 {%0, %1}, %2;" : "=f"(r.x), "=f"(r.y) : "l"(v)); return r;
}
__device__ __forceinline__ void fma2(ull& d, ull a, ull b) {
    asm("fma.rn.f32x2 %0, %1, %2, %0;" : "+l"(d) : "l"(a), "l"(b));
}
__device__ __forceinline__ float tf32r(float x) {
    float r; asm("cvt.rna.tf32.f32 %0, %1;" : "=f"(r) : "f"(x)); return r;
}
__device__ __forceinline__ uint32_t smem_u32(const void* p) {
    uint32_t a;
    asm("{ .reg .u64 t; cvta.to.shared.u64 t, %1; cvt.u32.u64 %0, t; }" : "=r"(a) : "l"(p));
    return a;
}
__device__ __forceinline__ void cp_async16(uint32_t dst, const void* src) {
    asm volatile("cp.async.cg.shared.global [%0], [%1], 16;" :: "r"(dst), "l"(src) : "memory");
}
__device__ __forceinline__ void mma_m16n8k8(float* c, const uint32_t* a,
                                            uint32_t b0, uint32_t b1) {
    asm volatile(
        "mma.sync.aligned.m16n8k8.row.col.f32.tf32.tf32.f32 "
        "{%0,%1,%2,%3}, {%4,%5,%6,%7}, {%8,%9}, {%0,%1,%2,%3};"
        : "+f"(c[0]), "+f"(c[1]), "+f"(c[2]), "+f"(c[3])
        : "r"(a[0]), "r"(a[1]), "r"(a[2]), "r"(a[3]), "r"(b0), "r"(b1));
}

__global__ void knop() {}

// ---------------------------------------------------------------------------
// Fused init: tf32-round x -> g_H, round weights, ring slot 1 <- h0^T, ctrs.
// ---------------------------------------------------------------------------
__global__ void fused_init(const float* __restrict__ x,
                           const float* __restrict__ Wih,
                           const float* __restrict__ Who,
                           const float* __restrict__ h0)
{
    int i = blockIdx.x * 256 + threadIdx.x;   // float4 idx
    float4 v = ((const float4*)x)[i];
    v.x = tf32r(v.x); v.y = tf32r(v.y); v.z = tf32r(v.z); v.w = tf32r(v.w);
    ((float4*)g_H)[i] = v;

    if (i < NF * NF) {
        int n = i >> 10, k = i & 1023;
        g_Wx[i]  = tf32r(Wih[(size_t)n * 2048 + k]);
        g_Who[i] = tf32r(Who[i]);
    }
    if (i < 65536) {
        int k = i >> 6, b = i & 63;
        g_ring[1032 * 64 + k * 64 + b] = h0[b * 1024 + k];
    }
    if (i < 2 * NS) g_ctr[i] = 0u;
}

// ---------------------------------------------------------------------------
// tf32 mma.sync GEMM v2: C[M x 1024] = A[M x 1024] @ B^T + bias.
// CTA tile 128m x 256n (halves L2 traffic vs 128x128), BK=32, 256 threads,
// 8 warps (warp tile 32m x 128n, 128 acc regs/thread), cp.async 2-stage.
// SMEM per stage: A[128][SST] + B[256][SST]. Grid (4 n-tiles, M/128).
// ---------------------------------------------------------------------------
__global__ void __launch_bounds__(256, 1) gemm_mma(
    const float* __restrict__ A, const float* __restrict__ B,
    const float* __restrict__ bias, float* __restrict__ C)
{
    extern __shared__ float sm[];
    const int tid = threadIdx.x;
    const int wid = tid >> 5, lane = tid & 31;
    const int g = lane >> 2, tig = lane & 3;
    const int bm = blockIdx.y * 128, bn = blockIdx.x * 256;
    const int wm = (wid & 3) * 32;       // warp m offset (4 warps over 128)
    const int wn = (wid >> 2) * 128;     // warp n offset (2 warps over 256)

    const int ABUF = 128 * SST;          // floats
    const int BBUF = 256 * SST;
    const int STAGE = ABUF + BBUF;
    const uint32_t sbase = smem_u32(sm);

    // loaders: A: row tid>>1, 16 floats at k=(tid&1)*16 (4 cp16)
    //          B: row tid, all 32 floats (8 cp16)
    const int arow = tid >> 1, ak = (tid & 1) * 16;
    const float* Ag = A + (size_t)(bm + arow) * 1024 + ak;
    const float* Bg = B + (size_t)(bn + tid) * 1024;
    const uint32_t dstA = sbase + (uint32_t)(arow * SST + ak) * 4;
    const uint32_t dstB = sbase + (uint32_t)(ABUF + tid * SST) * 4;

    float acc[2][16][4];
#pragma unroll
    for (int mt = 0; mt < 2; mt++)
#pragma unroll
        for (int nt = 0; nt < 16; nt++)
#pragma unroll
            for (int q = 0; q < 4; q++) acc[mt][nt][q] = 0.f;

    // preload stage 0
    {
#pragma unroll
        for (int j = 0; j < 4; j++) cp_async16(dstA + j * 16, Ag + 4 * j);
#pragma unroll
        for (int j = 0; j < 8; j++) cp_async16(dstB + j * 16, Bg + 4 * j);
        asm volatile("cp.async.commit_group;" ::: "memory");
    }

    for (int c = 0; c < 32; ++c) {
        if (c + 1 < 32) {
            const uint32_t off = (uint32_t)(((c + 1) & 1) * STAGE) * 4;
            const float* ag = Ag + (c + 1) * 32;
            const float* bg = Bg + (c + 1) * 32;
#pragma unroll
            for (int j = 0; j < 4; j++) cp_async16(dstA + off + j * 16, ag + 4 * j);
#pragma unroll
            for (int j = 0; j < 8; j++) cp_async16(dstB + off + j * 16, bg + 4 * j);
            asm volatile("cp.async.commit_group;" ::: "memory");
            asm volatile("cp.async.wait_group 1;" ::: "memory");
        } else {
            asm volatile("cp.async.wait_group 0;" ::: "memory");
        }
        __syncthreads();

        const float* As_ = sm + (c & 1) * STAGE;
        const float* Bs_ = As_ + ABUF;
#pragma unroll
        for (int ks = 0; ks < 4; ks++) {
            const int k = ks * 8;
            uint32_t a[2][4];
#pragma unroll
            for (int mt = 0; mt < 2; mt++) {
                const float* ap = As_ + (wm + mt * 16 + g) * SST + k + tig;
                a[mt][0] = __float_as_uint(ap[0]);
                a[mt][1] = __float_as_uint(ap[8 * SST]);
                a[mt][2] = __float_as_uint(ap[4]);
                a[mt][3] = __float_as_uint(ap[8 * SST + 4]);
            }
#pragma unroll
            for (int nt = 0; nt < 16; nt++) {
                const float* bp = Bs_ + (wn + nt * 8 + g) * SST + k + tig;
                uint32_t b0 = __float_as_uint(bp[0]);
                uint32_t b1 = __float_as_uint(bp[4]);
                mma_m16n8k8(acc[0][nt], a[0], b0, b1);
                mma_m16n8k8(acc[1][nt], a[1], b0, b1);
            }
        }
        __syncthreads();
    }

    // epilogue
#pragma unroll
    for (int mt = 0; mt < 2; mt++) {
        const size_t r0 = (size_t)(bm + wm + mt * 16 + g) * 1024;
#pragma unroll
        for (int nt = 0; nt < 16; nt++) {
            const int col = bn + wn + nt * 8 + 2 * tig;
            float2 bb = *(const float2*)&bias[col];
            float2 v0 = make_float2(acc[mt][nt][0] + bb.x, acc[mt][nt][1] + bb.y);
            float2 v1 = make_float2(acc[mt][nt][2] + bb.x, acc[mt][nt][3] + bb.y);
            *(float2*)&C[r0 + col] = v0;
            *(float2*)&C[r0 + 8 * 1024 + col] = v1;
        }
    }
}

// ---------------------------------------------------------------------------
// Persistent recurrence scan — ROUND 7 VERSION (best measured: 2.75 ms).
// 128 CTAs x 512 threads, 2 batch-groups of 64 CTAs. CTA owns 16 n; W_h
// n-major UNduplicated in SMEM (64 KB; keeps L1 large enough for the ring).
// ---------------------------------------------------------------------------
__global__ void __launch_bounds__(512, 1) rnn_scan(const float* __restrict__ Wih)
{
    extern __shared__ float smf[];
    float* wsm = smf;                    // [1024 k][16 n] n-major (64 KB)
    ull* red = (ull*)(smf + 16384);      // [16 w][8 q][32 lane] (32 KB)

    const int tid  = threadIdx.x;
    const int warp = tid >> 5, lane = tid & 31;
    const int bq = lane & 7;             // 4-batch group within 32
    const int nq = lane >> 3;            // 4-n group within 16
    const int kbase = warp * 64;
    const int grp = blockIdx.x & 1;      // batch group
    const int NB0 = (blockIdx.x >> 1) * 16;
    const int B0  = grp * 32;

    for (int idx = tid; idx < 16384; idx += 512) {
        int n = idx >> 10, k = idx & 1023;
        wsm[k * 16 + n] = Wih[(size_t)(NB0 + n) * 2048 + 1024 + k];
    }

    const int rq = tid >> 5, rl = tid & 31;            // valid for tid < 256
    const int rb = B0 + 4 * (rl & 7) + (rq >> 1);      // batch
    const int rn = NB0 + 4 * (rl >> 3) + 2 * (rq & 1); // even n
    const size_t pb = ((size_t)rb * NS) * NF + rn;

    __syncthreads();

    float2 pr = make_float2(0.f, 0.f);
    if (tid < 256) pr = *(const float2*)&g_P[pb];

    for (int s = 0; s < NS; ++s) {
        const float* __restrict__ hq =
            g_ring + ((s + 1) & 1) * (1032 * 64) + B0 + 4 * bq;

        ull acc[4][2];
#pragma unroll
        for (int i = 0; i < 4; i++) { acc[i][0] = 0ull; acc[i][1] = 0ull; }

        float4 pf[8];
#pragma unroll
        for (int j = 0; j < 8; ++j)
            pf[j] = *(const float4*)(hq + (kbase + j) * 64);
#pragma unroll 8
        for (int kk = 0; kk < 64; ++kk) {
            const int slot = kk & 7;
            float4 h = pf[slot];
            pf[slot] = *(const float4*)(hq + (kbase + kk + 8) * 64);
            ulonglong2 w = *(const ulonglong2*)(wsm + (kbase + kk) * 16 + 4 * nq);
            ull h0d = pack2(h.x), h1d = pack2(h.y);
            ull h2d = pack2(h.z), h3d = pack2(h.w);
            fma2(acc[0][0], h0d, w.x); fma2(acc[0][1], h0d, w.y);
            fma2(acc[1][0], h1d, w.x); fma2(acc[1][1], h1d, w.y);
            fma2(acc[2][0], h2d, w.x); fma2(acc[2][1], h2d, w.y);
            fma2(acc[3][0], h3d, w.x); fma2(acc[3][1], h3d, w.y);
        }

#pragma unroll
        for (int i = 0; i < 4; i++)
#pragma unroll
            for (int p = 0; p < 2; p++)
                red[((warp * 8) + (i * 2 + p)) * 32 + lane] = acc[i][p];
        __syncthreads();

        float r0 = 0.f, r1 = 0.f;
        if (tid < 256) {
            float sx = 0.f, sy = 0.f;
#pragma unroll
            for (int w2 = 0; w2 < 16; ++w2) {
                float2 v = unpack2(red[(w2 * 8 + rq) * 32 + rl]);
                sx += v.x; sy += v.y;
            }
            r0 = tanhf(sx + pr.x);
            r1 = tanhf(sy + pr.y);
            float* rc = g_ring + (s & 1) * (1032 * 64);
            rc[rn * 64 + rb] = r0;
            rc[(rn + 1) * 64 + rb] = r1;
        }

        if (s != NS - 1) {
            __syncthreads();
            if (tid == 0) {
                asm volatile("red.release.gpu.global.add.u32 [%0], %1;"
                             :: "l"(&g_ctr[s * 2 + grp]), "r"(1u) : "memory");
            }
            if (tid < 256) {
                *(float2*)&g_H[pb + (size_t)s * NF] =
                    make_float2(tf32r(r0), tf32r(r1));
                pr = *(const float2*)&g_P[pb + (size_t)(s + 1) * NF];
            }
            if (tid == 0) {
                unsigned v;
                do {
                    asm volatile("ld.acquire.gpu.global.u32 %0, [%1];"
                                 : "=r"(v) : "l"(&g_ctr[s * 2 + grp]));
                } while (v < 64u);
            }
            __syncthreads();
        } else {
            if (tid < 256) {
                *(float2*)&g_H[pb + (size_t)s * NF] =
                    make_float2(tf32r(r0), tf32r(r1));
            }
        }
    }
}

extern "C" void kernel_launch(void* const* d_in, const int* in_sizes, int n_in,
                              void* d_out, int out_size)
{
    const float* x   = (const float*)d_in[0];
    const float* h0  = (const float*)d_in[1];
    const float* Wih = (const float*)d_in[2];
    const float* bih = (const float*)d_in[3];
    const float* Who = (const float*)d_in[4];
    const float* bho = (const float*)d_in[5];
    float* out = (float*)d_out;

    float *pP = nullptr, *pH = nullptr, *pWx = nullptr, *pWo = nullptr;
    cudaGetSymbolAddress((void**)&pP, g_P);
    cudaGetSymbolAddress((void**)&pH, g_H);
    cudaGetSymbolAddress((void**)&pWx, g_Wx);
    cudaGetSymbolAddress((void**)&pWo, g_Who);

    const int GEMM_SMEM = 2 * (128 + 256) * SST * 4;   // 110592 B
    const int SCAN_SMEM = 98304;

    static bool attr_done = false;
    if (!attr_done) {
        cudaFuncSetAttribute(rnn_scan, cudaFuncAttributeMaxDynamicSharedMemorySize, SCAN_SMEM);
        cudaFuncSetAttribute(gemm_mma, cudaFuncAttributeMaxDynamicSharedMemorySize, GEMM_SMEM);
        attr_done = true;
    }

    // user idx 0: fused init
    fused_init<<<32768, 256>>>(x, Wih, Who, h0);
    // user idx 1: x_proj = x_r @ W_x^T + b_ih -> g_P
    gemm_mma<<<dim3(4, 256), 256, GEMM_SMEM>>>(pH, pWx, bih, pP);
    // user idx 2: pad so profiler (user idx 3) hits the scan
    knop<<<1, 32>>>();
    // user idx 3: persistent recurrence scan  <-- ncu capture
    rnn_scan<<<128, 512, SCAN_SMEM>>>(Wih);
    // user idx 4: out = h_r @ W_ho^T + b_ho
    gemm_mma<<<dim3(4, 256), 256, GEMM_SMEM>>>(pH, pWo, bho, out);
}